// round 17
// baseline (speedup 1.0000x reference)
#include <cuda_runtime.h>
#include <cuda_fp16.h>
#include <cuda_bf16.h>

#define N_NODES   10000
#define N_EDGES   640000
#define F_IN      128
#define H1        64
#define H2        32
#define N_CLASSES 16

// PDL device controls (sm_90+)
#define GDC_LAUNCH() asm volatile("griddepcontrol.launch_dependents;")
#define GDC_WAIT()   asm volatile("griddepcontrol.wait;" ::: "memory")

// ---------------- scratch (device globals) ----------------------------------
__device__ uint4 g_h1s [N_NODES * H1 / 8];   // h1 * dinv[n]  (fp16 payload)
__device__ uint4 g_agg1[N_NODES * H1 / 8];   // fp16 accum: init h1s + b1*rd
__device__ uint4 g_h2s [N_NODES * H2 / 8];   // h2 * dinv[n]  (fp16)
__device__ uint4 g_agg2[N_NODES * H2 / 8];   // fp16 accum: init h2s + b2*rd
__device__ int   g_deg [N_NODES];            // ALWAYS zero at launch entry
__device__ float g_colsum[H2];
__device__ unsigned g_ticket = 0;            // post2 last-block ticket

// 16-byte vectorized fp16 reduction (no return), sm_90+
__device__ __forceinline__ void red_add_v4_f16x2(void* addr, uint4 a) {
    asm volatile("red.global.add.noftz.v4.f16x2 [%0], {%1,%2,%3,%4};"
                 :: "l"(addr), "r"(a.x), "r"(a.y), "r"(a.z), "r"(a.w)
                 : "memory");
}

// ---------------- degree histogram (+ colsum zero), 2 edges/thread ------------
__global__ void hist_kernel(const int* __restrict__ ei) {
    GDC_LAUNCH();
    int t = blockIdx.x * blockDim.x + threadIdx.x;
    // prologue: ei is a constant harness input -> safe to read pre-wait
    int2 d2 = make_int2(0, 0);
    bool act = (t < N_EDGES / 2);
    if (act) d2 = *(const int2*)(ei + N_EDGES + t * 2);
    GDC_WAIT();   // orders against prior replay's post2 (deg/ticket reset)
    if (blockIdx.x == 0 && threadIdx.x < H2) g_colsum[threadIdx.x] = 0.0f;
    if (!act) return;
    atomicAdd(&g_deg[d2.x], 1);
    atomicAdd(&g_deg[d2.y], 1);
}

// ---------------- gemm1: h1 = x @ W1 -----------------------------------------
// 64 nodes x 64 outs, 256 threads, micro 4x4, two K chunks of 64.
// Matmul runs PRE-wait (x, W1 inputs only) -> overlaps with hist.
// epilogue (fp16, post-wait): h1s = h1*d;  agg1 = h1s + b1*rd
__global__ __launch_bounds__(256) void gemm1_kernel(const float* __restrict__ x,
                                                    const float* __restrict__ W1,
                                                    const float* __restrict__ b1) {
    GDC_LAUNCH();
    __shared__ float Ws[64][64];
    __shared__ float Xt[64][68];

    const int tid = threadIdx.x;
    const int tx  = tid & 15;
    const int ty  = tid >> 4;
    const int node0 = blockIdx.x * 64;

    float acc[4][4];
#pragma unroll
    for (int i = 0; i < 4; i++)
#pragma unroll
        for (int j = 0; j < 4; j++) acc[i][j] = 0.0f;

    for (int kc = 0; kc < 2; kc++) {
        {
            int r  = tid >> 4;
            int c4 = (tid & 15) * 4;
#pragma unroll
            for (int p = 0; p < 4; p++) {
                int rr = r + p * 16;
                *(float4*)(&Ws[rr][c4]) =
                    *(const float4*)(W1 + (kc * 64 + rr) * H1 + c4);
            }
        }
        {
            int nl = tid & 63;
            int kq = (tid >> 6) * 4;
            int node = node0 + nl;
#pragma unroll
            for (int p = 0; p < 4; p++) {
                int k4 = kq + p * 16;
                float4 v = make_float4(0.f, 0.f, 0.f, 0.f);
                if (node < N_NODES)
                    v = *(const float4*)(x + node * F_IN + kc * 64 + k4);
                Xt[k4 + 0][nl] = v.x; Xt[k4 + 1][nl] = v.y;
                Xt[k4 + 2][nl] = v.z; Xt[k4 + 3][nl] = v.w;
            }
        }
        __syncthreads();

#pragma unroll 8
        for (int k = 0; k < 64; k++) {
            float4 wv = *(const float4*)(&Ws[k][tx * 4]);
            float4 xv = *(const float4*)(&Xt[k][ty * 4]);
            acc[0][0] += xv.x * wv.x; acc[0][1] += xv.x * wv.y;
            acc[0][2] += xv.x * wv.z; acc[0][3] += xv.x * wv.w;
            acc[1][0] += xv.y * wv.x; acc[1][1] += xv.y * wv.y;
            acc[1][2] += xv.y * wv.z; acc[1][3] += xv.y * wv.w;
            acc[2][0] += xv.z * wv.x; acc[2][1] += xv.z * wv.y;
            acc[2][2] += xv.z * wv.z; acc[2][3] += xv.z * wv.w;
            acc[3][0] += xv.w * wv.x; acc[3][1] += xv.w * wv.y;
            acc[3][2] += xv.w * wv.z; acc[3][3] += xv.w * wv.w;
        }
        __syncthreads();
    }

    GDC_WAIT();   // need g_deg (hist) + write h1s/agg1 (prior replay readers)
    float4 bv = *(const float4*)(b1 + tx * 4);
#pragma unroll
    for (int i = 0; i < 4; i++) {
        int node = node0 + ty * 4 + i;
        if (node < N_NODES) {
            float dp1 = (float)g_deg[node] + 1.0f;
            float d   = rsqrtf(dp1);
            float rd  = dp1 * d;              // sqrt(deg+1)
            float4 hs = make_float4(acc[i][0] * d, acc[i][1] * d,
                                    acc[i][2] * d, acc[i][3] * d);
            __half2 hp0 = __floats2half2_rn(hs.x, hs.y);
            __half2 hp1 = __floats2half2_rn(hs.z, hs.w);
            *(uint2*)((__half*)g_h1s + node * H1 + tx * 4) =
                make_uint2(*(unsigned*)&hp0, *(unsigned*)&hp1);
            __half2 ap0 = __floats2half2_rn(hs.x + bv.x * rd, hs.y + bv.y * rd);
            __half2 ap1 = __floats2half2_rn(hs.z + bv.z * rd, hs.w + bv.w * rd);
            *(uint2*)((__half*)g_agg1 + node * H1 + tx * 4) =
                make_uint2(*(unsigned*)&ap0, *(unsigned*)&ap1);
        }
    }
}

// ---------------- edge aggregation layer 1 -----------------------------------
// Thread handles slice q of TWO consecutive edges; indices loaded pre-wait.
__global__ void agg1_kernel(const int* __restrict__ ei) {
    GDC_LAUNCH();
    long long t = (long long)blockIdx.x * blockDim.x + threadIdx.x;
    int ep = (int)(t >> 3);          // edge pair
    int q  = (int)(t & 7);
    bool act = (ep < N_EDGES / 2);
    int2 s2 = make_int2(0, 0), d2 = make_int2(0, 0);
    if (act) {
        s2 = *(const int2*)(ei + ep * 2);
        d2 = *(const int2*)(ei + N_EDGES + ep * 2);
    }
    GDC_WAIT();
    if (!act) return;
    uint4 a0 = g_h1s[s2.x * 8 + q];
    uint4 a1 = g_h1s[s2.y * 8 + q];
    red_add_v4_f16x2(g_agg1 + d2.x * 8 + q, a0);
    red_add_v4_f16x2(g_agg1 + d2.y * 8 + q, a1);
}

// ---------------- gemm2: h2 = relu(agg1*d) @ W2 ------------------------------
// 64 nodes x 32 outs, 128 threads, micro 4x4. W2 smem load pre-wait.
__global__ __launch_bounds__(128) void gemm2_kernel(const float* __restrict__ W2,
                                                    const float* __restrict__ b2) {
    GDC_LAUNCH();
    __shared__ float Ws[64][32];
    __shared__ float Xt[64][68];

    const int tid = threadIdx.x;
    const int tx  = tid & 7;
    const int ty  = tid >> 3;
    const int node0 = blockIdx.x * 64;

    {   // prologue: W2 is a harness input
        int r  = tid >> 3;
        int c4 = (tid & 7) * 4;
#pragma unroll
        for (int p = 0; p < 4; p++) {
            int rr = r + p * 16;
            *(float4*)(&Ws[rr][c4]) = *(const float4*)(W2 + rr * H2 + c4);
        }
    }
    GDC_WAIT();   // need g_agg1 (agg1) + g_deg
    {
        int nl = tid & 63;                 // node local
        int hsel = tid >> 6;               // 0/1 -> k half [0,32) or [32,64)
        int node = node0 + nl;
        float d = 0.f;
        if (node < N_NODES) d = rsqrtf((float)g_deg[node] + 1.0f);
#pragma unroll
        for (int p = 0; p < 4; p++) {
            int k8 = hsel * 32 + p * 8;
            uint4 raw = make_uint4(0, 0, 0, 0);
            if (node < N_NODES)
                raw = g_agg1[node * 8 + hsel * 4 + p];
            __half2* hp = (__half2*)&raw;
#pragma unroll
            for (int u = 0; u < 4; u++) {
                float2 f = __half22float2(hp[u]);
                Xt[k8 + u * 2 + 0][nl] = fmaxf(f.x * d, 0.f);
                Xt[k8 + u * 2 + 1][nl] = fmaxf(f.y * d, 0.f);
            }
        }
    }
    __syncthreads();

    float acc[4][4];
#pragma unroll
    for (int i = 0; i < 4; i++)
#pragma unroll
        for (int j = 0; j < 4; j++) acc[i][j] = 0.0f;

#pragma unroll 8
    for (int k = 0; k < 64; k++) {
        float4 wv = *(const float4*)(&Ws[k][tx * 4]);
        float4 xv = *(const float4*)(&Xt[k][ty * 4]);
        acc[0][0] += xv.x * wv.x; acc[0][1] += xv.x * wv.y;
        acc[0][2] += xv.x * wv.z; acc[0][3] += xv.x * wv.w;
        acc[1][0] += xv.y * wv.x; acc[1][1] += xv.y * wv.y;
        acc[1][2] += xv.y * wv.z; acc[1][3] += xv.y * wv.w;
        acc[2][0] += xv.z * wv.x; acc[2][1] += xv.z * wv.y;
        acc[2][2] += xv.z * wv.z; acc[2][3] += xv.z * wv.w;
        acc[3][0] += xv.w * wv.x; acc[3][1] += xv.w * wv.y;
        acc[3][2] += xv.w * wv.z; acc[3][3] += xv.w * wv.w;
    }

    float4 bv = *(const float4*)(b2 + tx * 4);
#pragma unroll
    for (int i = 0; i < 4; i++) {
        int node = node0 + ty * 4 + i;
        if (node < N_NODES) {
            float dp1 = (float)g_deg[node] + 1.0f;
            float d   = rsqrtf(dp1);
            float rd  = dp1 * d;
            float4 hs = make_float4(acc[i][0] * d, acc[i][1] * d,
                                    acc[i][2] * d, acc[i][3] * d);
            __half2 hp0 = __floats2half2_rn(hs.x, hs.y);
            __half2 hp1 = __floats2half2_rn(hs.z, hs.w);
            *(uint2*)((__half*)g_h2s + node * H2 + tx * 4) =
                make_uint2(*(unsigned*)&hp0, *(unsigned*)&hp1);
            __half2 ap0 = __floats2half2_rn(hs.x + bv.x * rd, hs.y + bv.y * rd);
            __half2 ap1 = __floats2half2_rn(hs.z + bv.z * rd, hs.w + bv.w * rd);
            *(uint2*)((__half*)g_agg2 + node * H2 + tx * 4) =
                make_uint2(*(unsigned*)&ap0, *(unsigned*)&ap1);
        }
    }
}

// ---------------- edge aggregation layer 2 -----------------------------------
// Thread handles slice q of TWO consecutive edges; indices loaded pre-wait.
__global__ void agg2_kernel(const int* __restrict__ ei) {
    GDC_LAUNCH();
    long long t = (long long)blockIdx.x * blockDim.x + threadIdx.x;
    int ep = (int)(t >> 2);          // edge pair
    int q  = (int)(t & 3);
    bool act = (ep < N_EDGES / 2);
    int2 s2 = make_int2(0, 0), d2 = make_int2(0, 0);
    if (act) {
        s2 = *(const int2*)(ei + ep * 2);
        d2 = *(const int2*)(ei + N_EDGES + ep * 2);
    }
    GDC_WAIT();
    if (!act) return;
    uint4 a0 = g_h2s[s2.x * 4 + q];
    uint4 a1 = g_h2s[s2.y * 4 + q];
    red_add_v4_f16x2(g_agg2 + d2.x * 4 + q, a0);
    red_add_v4_f16x2(g_agg2 + d2.y * 4 + q, a1);
}

// ---------------- post2 + final (last-block pattern) ---------------------------
__global__ void post2_kernel(const float* __restrict__ Wfc,
                             const float* __restrict__ bfc,
                             float* __restrict__ out) {
    GDC_LAUNCH();
    GDC_WAIT();
    __shared__ float s[512];
    __shared__ bool last;
    int t = blockIdx.x * blockDim.x + threadIdx.x;   // over N_NODES*16
    float v0 = 0.0f, v1 = 0.0f;
    if (t < N_NODES * 16) {
        int n = t >> 4;
        float d = rsqrtf((float)g_deg[n] + 1.0f);
        unsigned raw = ((const unsigned*)g_agg2)[t];   // 2 halves
        float2 f = __half22float2(*(__half2*)&raw);
        v0 = fmaxf(f.x * d, 0.0f);
        v1 = fmaxf(f.y * d, 0.0f);
    }
    s[threadIdx.x * 2 + 0] = v0;
    s[threadIdx.x * 2 + 1] = v1;
    __syncthreads();
#pragma unroll
    for (int st = 128; st >= 16; st >>= 1) {
        if (threadIdx.x < st) {
            s[threadIdx.x * 2 + 0] += s[(threadIdx.x + st) * 2 + 0];
            s[threadIdx.x * 2 + 1] += s[(threadIdx.x + st) * 2 + 1];
        }
        __syncthreads();
    }
    if (threadIdx.x < 16) {
        atomicAdd(&g_colsum[threadIdx.x * 2 + 0], s[threadIdx.x * 2 + 0]);
        atomicAdd(&g_colsum[threadIdx.x * 2 + 1], s[threadIdx.x * 2 + 1]);
    }
    __threadfence();
    if (threadIdx.x == 0)
        last = (atomicAdd(&g_ticket, 1u) == gridDim.x - 1);
    __syncthreads();
    if (last) {
        __threadfence();                       // acquire: see all colsum adds
        for (int i = threadIdx.x; i < N_NODES; i += blockDim.x) g_deg[i] = 0;
        if (threadIdx.x < N_CLASSES) {
            int c = threadIdx.x;
            float acc = bfc[c];
            const float inv_n = 1.0f / (float)N_NODES;
#pragma unroll
            for (int f = 0; f < H2; f++)
                acc += (__ldcg(&g_colsum[f]) * inv_n) * Wfc[f * N_CLASSES + c];
            out[c] = acc;
        }
        if (threadIdx.x == 0) g_ticket = 0;    // reset ticket for next replay
    }
}

// ---------------- launch (PDL on every kernel) --------------------------------
template <typename F, typename... Args>
static inline void launch_pdl(F kern, int grid, int block, Args... args) {
    cudaLaunchConfig_t cfg = {};
    cfg.gridDim  = dim3(grid);
    cfg.blockDim = dim3(block);
    cfg.stream   = 0;
    cudaLaunchAttribute attr[1];
    attr[0].id = cudaLaunchAttributeProgrammaticStreamSerialization;
    attr[0].val.programmaticStreamSerializationAllowed = 1;
    cfg.attrs = attr;
    cfg.numAttrs = 1;
    cudaLaunchKernelEx(&cfg, kern, args...);
}

extern "C" void kernel_launch(void* const* d_in, const int* in_sizes, int n_in,
                              void* d_out, int out_size) {
    const float* x   = (const float*)d_in[0];
    const float* W1  = (const float*)d_in[1];
    const float* b1  = (const float*)d_in[2];
    const float* W2  = (const float*)d_in[3];
    const float* b2  = (const float*)d_in[4];
    const float* Wfc = (const float*)d_in[5];
    const float* bfc = (const float*)d_in[6];
    const int*   ei  = (const int*)  d_in[7];
    float* out = (float*)d_out;

    launch_pdl(hist_kernel,  N_EDGES / 2 / 256, 256, ei);
    launch_pdl(gemm1_kernel, (N_NODES + 63) / 64, 256, x, W1, b1);
    launch_pdl(agg1_kernel,  N_EDGES / 2 * 8 / 256, 256, ei);
    launch_pdl(gemm2_kernel, (N_NODES + 63) / 64, 128, W2, b2);
    launch_pdl(agg2_kernel,  N_EDGES / 2 * 4 / 256, 256, ei);
    launch_pdl(post2_kernel, (N_NODES * 16 + 255) / 256, 256, Wfc, bfc, out);
}